// round 4
// baseline (speedup 1.0000x reference)
#include <cuda_runtime.h>
#include <math.h>

#define BB 4
#define SS 8192
#define DD 512
#define HH 8
#define DH 64
#define MT (BB*SS)          // 32768 rows
#define NCH 8
#define SCH (SS/NCH)        // 1024

// ---------------- scratch (alloc-free: __device__ globals) ----------------
__device__ float g_qf [MT*DD];              // elu(q@Wq^T+bq)+1
__device__ float g_kf [MT*DD];              // elu(k@Wk^T+bk)+1
__device__ float g_vv [MT*DD];              // v@Wv^T+bv
__device__ float g_att[MT*DD];              // attention out before Wo
__device__ float g_kvp[BB*HH*NCH*DH*DH];    // kv partials per s-chunk
__device__ float g_zp [BB*HH*NCH*DH];       // z partials
__device__ float g_kv [BB*HH*DH*DH];        // reduced kv
__device__ float g_z  [BB*HH*DH];           // reduced z

// ---------------- GEMM: C[M,N] = A[M,K] @ W[N,K]^T + bias, optional elu+1 ---
// BM=128, BN=64, BK=16, 256 threads, 8x4 per-thread microtile.
template<int ACT>
__global__ __launch_bounds__(256) void gemm_xwt(const float* __restrict__ A,
                                                const float* __restrict__ W,
                                                const float* __restrict__ bias,
                                                float* __restrict__ C) {
    const int K = DD, N = DD;
    __shared__ float As[16][132];   // [k][m], padded
    __shared__ float Bs[16][68];    // [k][n], padded
    int tid = threadIdx.x;
    int bm = blockIdx.y * 128;
    int bn = blockIdx.x * 64;
    int tx = tid & 15, ty = tid >> 4;

    float acc[8][4];
#pragma unroll
    for (int i = 0; i < 8; i++)
#pragma unroll
        for (int j = 0; j < 4; j++) acc[i][j] = 0.f;

    for (int k0 = 0; k0 < K; k0 += 16) {
        // load A tile 128x16 (2 float4 per thread), store transposed
#pragma unroll
        for (int i = 0; i < 2; i++) {
            int idx = tid * 2 + i;
            int r = idx >> 2, c = (idx & 3) * 4;
            float4 va = *(const float4*)&A[(size_t)(bm + r) * K + k0 + c];
            As[c + 0][r] = va.x; As[c + 1][r] = va.y;
            As[c + 2][r] = va.z; As[c + 3][r] = va.w;
        }
        // load W tile 64x16 (1 float4 per thread), store transposed
        {
            int r = tid >> 2, c = (tid & 3) * 4;
            float4 vb = *(const float4*)&W[(size_t)(bn + r) * K + k0 + c];
            Bs[c + 0][r] = vb.x; Bs[c + 1][r] = vb.y;
            Bs[c + 2][r] = vb.z; Bs[c + 3][r] = vb.w;
        }
        __syncthreads();
#pragma unroll
        for (int kk = 0; kk < 16; kk++) {
            float a[8], b[4];
#pragma unroll
            for (int i = 0; i < 8; i++) a[i] = As[kk][ty * 8 + i];
#pragma unroll
            for (int j = 0; j < 4; j++) b[j] = Bs[kk][tx * 4 + j];
#pragma unroll
            for (int i = 0; i < 8; i++)
#pragma unroll
                for (int j = 0; j < 4; j++)
                    acc[i][j] = fmaf(a[i], b[j], acc[i][j]);
        }
        __syncthreads();
    }

    int colb = bn + tx * 4;
    float b0 = bias[colb + 0], b1 = bias[colb + 1], b2 = bias[colb + 2], b3 = bias[colb + 3];
#pragma unroll
    for (int i = 0; i < 8; i++) {
        int row = bm + ty * 8 + i;
        float4 o;
        o.x = acc[i][0] + b0; o.y = acc[i][1] + b1;
        o.z = acc[i][2] + b2; o.w = acc[i][3] + b3;
        if (ACT) {
            o.x = (o.x > 0.f) ? (o.x + 1.f) : expf(o.x);
            o.y = (o.y > 0.f) ? (o.y + 1.f) : expf(o.y);
            o.z = (o.z > 0.f) ? (o.z + 1.f) : expf(o.z);
            o.w = (o.w > 0.f) ? (o.w + 1.f) : expf(o.w);
        }
        *(float4*)&C[(size_t)row * N + colb] = o;
    }
}

// ---------------- kv/z partial sums over one s-chunk per block --------------
// grid (NCH, HH, BB), 256 threads; each thread owns a 4x4 block of kv[64,64].
__global__ __launch_bounds__(256) void kv_partial() {
    int ch = blockIdx.x, h = blockIdx.y, b = blockIdx.z;
    __shared__ float ks[32][68];
    __shared__ float vs[32][68];
    int tid = threadIdx.x;
    int tx = tid & 15, ty = tid >> 4;
    int d0 = ty * 4, m0 = tx * 4;

    float acc[4][4];
#pragma unroll
    for (int i = 0; i < 4; i++)
#pragma unroll
        for (int j = 0; j < 4; j++) acc[i][j] = 0.f;
    float zacc = 0.f;

    int s0 = ch * SCH;
    for (int st = 0; st < SCH; st += 32) {
#pragma unroll
        for (int i = 0; i < 2; i++) {
            int idx = tid + i * 256;
            int r = idx >> 4, c = (idx & 15) * 4;
            size_t base = (size_t)(b * SS + s0 + st + r) * DD + h * DH + c;
            *(float4*)&ks[r][c] = *(const float4*)&g_kf[base];
            *(float4*)&vs[r][c] = *(const float4*)&g_vv[base];
        }
        __syncthreads();
#pragma unroll 4
        for (int s = 0; s < 32; s++) {
            float a[4], v4[4];
#pragma unroll
            for (int i = 0; i < 4; i++) a[i]  = ks[s][d0 + i];
#pragma unroll
            for (int j = 0; j < 4; j++) v4[j] = vs[s][m0 + j];
#pragma unroll
            for (int i = 0; i < 4; i++)
#pragma unroll
                for (int j = 0; j < 4; j++)
                    acc[i][j] = fmaf(a[i], v4[j], acc[i][j]);
        }
        if (tid < DH) {
#pragma unroll 8
            for (int s = 0; s < 32; s++) zacc += ks[s][tid];
        }
        __syncthreads();
    }

    int bh = b * HH + h;
    float* kvp = &g_kvp[(size_t)(bh * NCH + ch) * DH * DH];
#pragma unroll
    for (int i = 0; i < 4; i++)
#pragma unroll
        for (int j = 0; j < 4; j++)
            kvp[(d0 + i) * DH + m0 + j] = acc[i][j];
    if (tid < DH) g_zp[(bh * NCH + ch) * DH + tid] = zacc;
}

// ---------------- deterministic chunk reduce + write kv/z outputs ----------
__global__ __launch_bounds__(256) void kv_reduce(float* kv_out, float* z_out) {
    int bh = blockIdx.x, tid = threadIdx.x;
#pragma unroll
    for (int e = 0; e < 16; e++) {
        int idx = e * 256 + tid;
        float s = 0.f;
#pragma unroll
        for (int ch = 0; ch < NCH; ch++)
            s += g_kvp[(size_t)(bh * NCH + ch) * DH * DH + idx];
        g_kv[(size_t)bh * DH * DH + idx] = s;
        if (kv_out) kv_out[(size_t)bh * DH * DH + idx] = s;
    }
    if (tid < DH) {
        float s = 0.f;
#pragma unroll
        for (int ch = 0; ch < NCH; ch++)
            s += g_zp[(bh * NCH + ch) * DH + tid];
        g_z[bh * DH + tid] = s;
        if (z_out) z_out[bh * DH + tid] = s;
    }
}

// ---------------- per-row apply: num = q@kv, den = q.z, out = num/(den+eps) -
// grid (SS/128, HH, BB), 128 threads; one s-row per thread, kv in smem.
__global__ __launch_bounds__(128) void attn_apply() {
    int b = blockIdx.z, h = blockIdx.y, st = blockIdx.x * 128;
    __shared__ float kvs[DH][DH];
    __shared__ float zs[DH];
    int tid = threadIdx.x;
    int bh = b * HH + h;

#pragma unroll
    for (int i = 0; i < 8; i++) {
        int idx = tid + i * 128;   // 1024 float4s
        *(float4*)&((float*)kvs)[idx * 4] =
            *(const float4*)&g_kv[(size_t)bh * DH * DH + idx * 4];
    }
    if (tid < 16)
        *(float4*)&zs[tid * 4] = *(const float4*)&g_z[bh * DH + tid * 4];
    __syncthreads();

    int s = st + tid;
    const float* qrow = &g_qf[(size_t)(b * SS + s) * DD + h * DH];

    float acc[DH];
#pragma unroll
    for (int m = 0; m < DH; m++) acc[m] = 0.f;
    float den = 0.f;

#pragma unroll 4
    for (int d = 0; d < DH; d++) {
        float qd = __ldg(&qrow[d]);
        den = fmaf(qd, zs[d], den);
#pragma unroll
        for (int m = 0; m < DH; m++)
            acc[m] = fmaf(qd, kvs[d][m], acc[m]);
    }

    float inv = 1.f / (den + 1e-6f);
    float* orow = &g_att[(size_t)(b * SS + s) * DD + h * DH];
#pragma unroll
    for (int i = 0; i < 16; i++) {
        float4 o;
        o.x = acc[i * 4 + 0] * inv; o.y = acc[i * 4 + 1] * inv;
        o.z = acc[i * 4 + 2] * inv; o.w = acc[i * 4 + 3] * inv;
        *(float4*)&orow[i * 4] = o;
    }
}

// ---------------- launch ----------------------------------------------------
extern "C" void kernel_launch(void* const* d_in, const int* in_sizes, int n_in,
                              void* d_out, int out_size) {
    (void)n_in; (void)in_sizes;
    const float* q  = (const float*)d_in[0];
    const float* k  = (const float*)d_in[1];
    const float* v  = (const float*)d_in[2];
    const float* Wq = (const float*)d_in[3];
    const float* bq = (const float*)d_in[4];
    const float* Wk = (const float*)d_in[5];
    const float* bk = (const float*)d_in[6];
    const float* Wv = (const float*)d_in[7];
    const float* bv = (const float*)d_in[8];
    const float* Wo = (const float*)d_in[9];
    const float* bo = (const float*)d_in[10];
    float* out = (float*)d_out;

    float *qf, *kf, *vv, *att;
    cudaGetSymbolAddress((void**)&qf,  g_qf);
    cudaGetSymbolAddress((void**)&kf,  g_kf);
    cudaGetSymbolAddress((void**)&vv,  g_vv);
    cudaGetSymbolAddress((void**)&att, g_att);

    dim3 gg(DD / 64, MT / 128);
    gemm_xwt<1><<<gg, 256>>>(q, Wq, bq, qf);
    gemm_xwt<1><<<gg, 256>>>(k, Wk, bk, kf);
    gemm_xwt<0><<<gg, 256>>>(v, Wv, bv, vv);

    kv_partial<<<dim3(NCH, HH, BB), 256>>>();

    float* kv_out = 0;
    float* z_out  = 0;
    if (out_size >= MT * DD + BB * HH * DH * DH + BB * HH * DH) {
        kv_out = out + (size_t)MT * DD;
        z_out  = kv_out + BB * HH * DH * DH;
    }
    kv_reduce<<<BB * HH, 256>>>(kv_out, z_out);

    attn_apply<<<dim3(SS / 128, HH, BB), 128>>>();

    gemm_xwt<0><<<gg, 256>>>(att, Wo, bo, out);
}